// round 8
// baseline (speedup 1.0000x reference)
#include <cuda_runtime.h>
#include <cuda_bf16.h>

// BitGatConv — algebraic collapse (verified R1-R4, rel_err ~1e-7):
//   vals[i,c] = nhs[i,c] * sum_j softmax(...)[i,j,c] = nhs[i,c]
// => out = nodes_ft @ weight  : [1536,256] @ [256,64]
//
// R6: 2x4 register blocking (each weight float4 feeds 2 rows), weight read
// straight from L1 (no smem staging, no mid-kernel phases), K-split x4,
// single-wave grid of 128 blocks x 384 threads.

#define NROWS        1536
#define KDIM         256
#define K4           (KDIM / 4)        // 64 float4 per row
#define HCDIM        64
#define ROWS_PER_BLK 12
#define RP           (ROWS_PER_BLK / 2) // 6 row-pairs
#define GRID         (NROWS / ROWS_PER_BLK)  // 128
#define KSPLIT       4
#define THREADS      (RP * 16 * KSPLIT)      // 384
#define K4_PER_TH    (K4 / KSPLIT)           // 16
#define NF_Q         (ROWS_PER_BLK * K4)     // 768 float4 = 12 KB

__global__ __launch_bounds__(THREADS)
void bitgat_nhs_kernel(const float* __restrict__ nodes_ft,
                       const float* __restrict__ weight,
                       float* __restrict__ out)
{
    __shared__ float4 s_nf[NF_Q];                       // 12 KB node tile
    __shared__ float4 s_red[(KSPLIT - 1) * RP * 16 * 2]; // 9 KB split-K partials

    const int tid  = threadIdx.x;
    const int row0 = blockIdx.x * ROWS_PER_BLK;

    const int kh  = tid / (RP * 16);      // 0..3  K quarter
    const int rem = tid % (RP * 16);
    const int r   = rem >> 4;             // 0..5  row pair (rows r, r+RP)
    const int cq  = rem & 15;             // 0..15 col quad

    const float4* __restrict__ wq  = reinterpret_cast<const float4*>(weight);
    const float4* __restrict__ src = reinterpret_cast<const float4*>(nodes_ft + (size_t)row0 * KDIM);

    // ---- stage node tile: 768 float4, 2 per thread ----
    s_nf[tid]           = src[tid];
    s_nf[tid + THREADS] = src[tid + THREADS];
    __syncthreads();

    const float4* __restrict__ a0 = &s_nf[ r       * K4 + kh * K4_PER_TH];
    const float4* __restrict__ a1 = &s_nf[(r + RP) * K4 + kh * K4_PER_TH];
    const float4* __restrict__ w  = &wq[(size_t)(kh * K4_PER_TH) * 4 * 16];

    float4 acc0 = make_float4(0.f, 0.f, 0.f, 0.f);
    float4 acc1 = make_float4(0.f, 0.f, 0.f, 0.f);

    #pragma unroll 4
    for (int k4 = 0; k4 < K4_PER_TH; ++k4) {
        const float4 av0 = a0[k4];                    // LDS.128 (2 distinct/warp)
        const float4 av1 = a1[k4];
        const float4 w0  = w[(4 * k4 + 0) * 16 + cq]; // LDG.128, L1-resident
        const float4 w1  = w[(4 * k4 + 1) * 16 + cq];
        const float4 w2  = w[(4 * k4 + 2) * 16 + cq];
        const float4 w3  = w[(4 * k4 + 3) * 16 + cq];

        acc0.x = fmaf(av0.x, w0.x, acc0.x); acc1.x = fmaf(av1.x, w0.x, acc1.x);
        acc0.y = fmaf(av0.x, w0.y, acc0.y); acc1.y = fmaf(av1.x, w0.y, acc1.y);
        acc0.z = fmaf(av0.x, w0.z, acc0.z); acc1.z = fmaf(av1.x, w0.z, acc1.z);
        acc0.w = fmaf(av0.x, w0.w, acc0.w); acc1.w = fmaf(av1.x, w0.w, acc1.w);

        acc0.x = fmaf(av0.y, w1.x, acc0.x); acc1.x = fmaf(av1.y, w1.x, acc1.x);
        acc0.y = fmaf(av0.y, w1.y, acc0.y); acc1.y = fmaf(av1.y, w1.y, acc1.y);
        acc0.z = fmaf(av0.y, w1.z, acc0.z); acc1.z = fmaf(av1.y, w1.z, acc1.z);
        acc0.w = fmaf(av0.y, w1.w, acc0.w); acc1.w = fmaf(av1.y, w1.w, acc1.w);

        acc0.x = fmaf(av0.z, w2.x, acc0.x); acc1.x = fmaf(av1.z, w2.x, acc1.x);
        acc0.y = fmaf(av0.z, w2.y, acc0.y); acc1.y = fmaf(av1.z, w2.y, acc1.y);
        acc0.z = fmaf(av0.z, w2.z, acc0.z); acc1.z = fmaf(av1.z, w2.z, acc1.z);
        acc0.w = fmaf(av0.z, w2.w, acc0.w); acc1.w = fmaf(av1.z, w2.w, acc1.w);

        acc0.x = fmaf(av0.w, w3.x, acc0.x); acc1.x = fmaf(av1.w, w3.x, acc1.x);
        acc0.y = fmaf(av0.w, w3.y, acc0.y); acc1.y = fmaf(av1.w, w3.y, acc1.y);
        acc0.z = fmaf(av0.w, w3.z, acc0.z); acc1.z = fmaf(av1.w, w3.z, acc1.z);
        acc0.w = fmaf(av0.w, w3.w, acc0.w); acc1.w = fmaf(av1.w, w3.w, acc1.w);
    }

    // ---- split-K reduction: kh>0 publish, kh==0 combines + stores ----
    __syncthreads();   // also guards s_nf reuse ordering
    if (kh > 0) {
        float4* p = &s_red[((kh - 1) * RP * 16 + rem) * 2];
        p[0] = acc0;
        p[1] = acc1;
    }
    __syncthreads();
    if (kh == 0) {
        #pragma unroll
        for (int s = 0; s < KSPLIT - 1; ++s) {
            const float4* p = &s_red[(s * RP * 16 + rem) * 2];
            const float4 q0 = p[0];
            const float4 q1 = p[1];
            acc0.x += q0.x; acc0.y += q0.y; acc0.z += q0.z; acc0.w += q0.w;
            acc1.x += q1.x; acc1.y += q1.y; acc1.z += q1.z; acc1.w += q1.w;
        }
        float4* dst0 = reinterpret_cast<float4*>(out + (size_t)(row0 + r)      * HCDIM);
        float4* dst1 = reinterpret_cast<float4*>(out + (size_t)(row0 + r + RP) * HCDIM);
        dst0[cq] = acc0;   // STG.128
        dst1[cq] = acc1;
    }
}

extern "C" void kernel_launch(void* const* d_in, const int* in_sizes, int n_in,
                              void* d_out, int out_size)
{
    // metadata order: nodes_ft, adj_bias_mat, weight, conv_weight1, conv_weight2
    const float* nodes_ft = (const float*)d_in[0];
    const float* weight   = (const float*)d_in[2];
    float* out = (float*)d_out;

    (void)in_sizes; (void)n_in; (void)out_size;

    bitgat_nhs_kernel<<<GRID, THREADS>>>(nodes_ft, weight, out);
}

// round 9
// speedup vs baseline: 1.2984x; 1.2984x over previous
#include <cuda_runtime.h>
#include <cuda_bf16.h>

// BitGatConv — algebraic collapse (verified R1-R6, rel_err ~1e-7):
//   vals[i,c] = nhs[i,c] * sum_j softmax(...)[i,j,c] = nhs[i,c]
// => out = nodes_ft @ weight  : [1536,256] @ [256,64]
//
// R8: occupancy-first. KSPLIT=8 -> 768 threads/block (24 warps/SM, ~38% occ)
// to hide weight LDG latency (what killed R6 at 12 warps). 2-row x 4-col
// register blocking keeps the LDG count at 4 per 32 FMAs. Single sync for
// the node tile; 7-way split-K reduce in smem.

#define NROWS        1536
#define KDIM         256
#define K4           (KDIM / 4)         // 64 float4 per row
#define HCDIM        64
#define ROWS_PER_BLK 12
#define RP           (ROWS_PER_BLK / 2) // 6 row-pairs
#define GRID         (NROWS / ROWS_PER_BLK)   // 128 blocks = single wave
#define KSPLIT       8
#define GROUP        (RP * 16)                // 96 threads per K-slice
#define THREADS      (GROUP * KSPLIT)         // 768
#define K4_PER_TH    (K4 / KSPLIT)            // 8
#define NF_Q         (ROWS_PER_BLK * K4)      // 768 float4 = 12 KB

__global__ __launch_bounds__(THREADS)
void bitgat_nhs_kernel(const float* __restrict__ nodes_ft,
                       const float* __restrict__ weight,
                       float* __restrict__ out)
{
    __shared__ float4 s_nf[NF_Q];                          // 12 KB node tile
    __shared__ float4 s_red[(KSPLIT - 1) * GROUP * 2];     // 21 KB partials

    const int tid  = threadIdx.x;
    const int row0 = blockIdx.x * ROWS_PER_BLK;

    const int kh  = tid / GROUP;          // 0..7  K-eighth
    const int rem = tid % GROUP;
    const int r   = rem >> 4;             // 0..5  row pair (rows r, r+RP)
    const int cq  = rem & 15;             // 0..15 col quad

    const float4* __restrict__ wq  = reinterpret_cast<const float4*>(weight);
    const float4* __restrict__ src = reinterpret_cast<const float4*>(nodes_ft + (size_t)row0 * KDIM);

    // ---- stage node tile: 768 float4, exactly 1 per thread ----
    s_nf[tid] = src[tid];
    __syncthreads();

    const float4* __restrict__ a0 = &s_nf[ r       * K4 + kh * K4_PER_TH];
    const float4* __restrict__ a1 = &s_nf[(r + RP) * K4 + kh * K4_PER_TH];
    const float4* __restrict__ w  = &wq[(size_t)(kh * K4_PER_TH * 4) * 16 + cq];

    float4 acc0 = make_float4(0.f, 0.f, 0.f, 0.f);
    float4 acc1 = make_float4(0.f, 0.f, 0.f, 0.f);

    #pragma unroll
    for (int k4 = 0; k4 < K4_PER_TH; ++k4) {
        const float4 av0 = a0[k4];                 // LDS.128, 2-way broadcast
        const float4 av1 = a1[k4];
        const float4 w0  = w[(4 * k4 + 0) * 16];   // LDG.128, independent addrs
        const float4 w1  = w[(4 * k4 + 1) * 16];
        const float4 w2  = w[(4 * k4 + 2) * 16];
        const float4 w3  = w[(4 * k4 + 3) * 16];

        acc0.x = fmaf(av0.x, w0.x, acc0.x); acc1.x = fmaf(av1.x, w0.x, acc1.x);
        acc0.y = fmaf(av0.x, w0.y, acc0.y); acc1.y = fmaf(av1.x, w0.y, acc1.y);
        acc0.z = fmaf(av0.x, w0.z, acc0.z); acc1.z = fmaf(av1.x, w0.z, acc1.z);
        acc0.w = fmaf(av0.x, w0.w, acc0.w); acc1.w = fmaf(av1.x, w0.w, acc1.w);

        acc0.x = fmaf(av0.y, w1.x, acc0.x); acc1.x = fmaf(av1.y, w1.x, acc1.x);
        acc0.y = fmaf(av0.y, w1.y, acc0.y); acc1.y = fmaf(av1.y, w1.y, acc1.y);
        acc0.z = fmaf(av0.y, w1.z, acc0.z); acc1.z = fmaf(av1.y, w1.z, acc1.z);
        acc0.w = fmaf(av0.y, w1.w, acc0.w); acc1.w = fmaf(av1.y, w1.w, acc1.w);

        acc0.x = fmaf(av0.z, w2.x, acc0.x); acc1.x = fmaf(av1.z, w2.x, acc1.x);
        acc0.y = fmaf(av0.z, w2.y, acc0.y); acc1.y = fmaf(av1.z, w2.y, acc1.y);
        acc0.z = fmaf(av0.z, w2.z, acc0.z); acc1.z = fmaf(av1.z, w2.z, acc1.z);
        acc0.w = fmaf(av0.z, w2.w, acc0.w); acc1.w = fmaf(av1.z, w2.w, acc1.w);

        acc0.x = fmaf(av0.w, w3.x, acc0.x); acc1.x = fmaf(av1.w, w3.x, acc1.x);
        acc0.y = fmaf(av0.w, w3.y, acc0.y); acc1.y = fmaf(av1.w, w3.y, acc1.y);
        acc0.z = fmaf(av0.w, w3.z, acc0.z); acc1.z = fmaf(av1.w, w3.z, acc1.z);
        acc0.w = fmaf(av0.w, w3.w, acc0.w); acc1.w = fmaf(av1.w, w3.w, acc1.w);
    }

    // ---- split-K reduction: kh>0 publish, kh==0 combines + stores ----
    if (kh > 0) {
        float4* p = &s_red[((kh - 1) * GROUP + rem) * 2];
        p[0] = acc0;
        p[1] = acc1;
    }
    __syncthreads();
    if (kh == 0) {
        #pragma unroll
        for (int s = 0; s < KSPLIT - 1; ++s) {
            const float4* p = &s_red[(s * GROUP + rem) * 2];
            const float4 q0 = p[0];
            const float4 q1 = p[1];
            acc0.x += q0.x; acc0.y += q0.y; acc0.z += q0.z; acc0.w += q0.w;
            acc1.x += q1.x; acc1.y += q1.y; acc1.z += q1.z; acc1.w += q1.w;
        }
        float4* dst0 = reinterpret_cast<float4*>(out + (size_t)(row0 + r)      * HCDIM);
        float4* dst1 = reinterpret_cast<float4*>(out + (size_t)(row0 + r + RP) * HCDIM);
        dst0[cq] = acc0;   // STG.128
        dst1[cq] = acc1;
    }
}

extern "C" void kernel_launch(void* const* d_in, const int* in_sizes, int n_in,
                              void* d_out, int out_size)
{
    // metadata order: nodes_ft, adj_bias_mat, weight, conv_weight1, conv_weight2
    const float* nodes_ft = (const float*)d_in[0];
    const float* weight   = (const float*)d_in[2];
    float* out = (float*)d_out;

    (void)in_sizes; (void)n_in; (void)out_size;

    bitgat_nhs_kernel<<<GRID, THREADS>>>(nodes_ft, weight, out);
}